// round 4
// baseline (speedup 1.0000x reference)
#include <cuda_runtime.h>

#define N_NODES  100000
#define N_EDGES  1600000
#define IN_DIM   500
#define HID      32
#define N_REL    7
#define OUT_DIM  4
#define N_GRAPHS 16
#define NCOL     256   // 32 root cols + 7*32 relation cols

// ---------------- scratch (device globals: allocation-free) ----------------
__device__ float g_H[(size_t)N_NODES * NCOL];          // 102.4 MB: node_x @ [W_root|W_rel]
__device__ float g_S[(size_t)N_NODES * N_REL * HID];   // 89.6 MB: per-(dst,rel) message sums
__device__ float g_cnt[(size_t)N_NODES * N_REL];       // 2.8 MB: per-(dst,rel) edge counts
__device__ float g_W[IN_DIM * NCOL];                   // 0.5 MB: concatenated weights
__device__ float g_pool[N_GRAPHS * HID];               // pooled relu outputs

// ---------------- zero scratch that is accumulated into --------------------
__global__ void zero_kernel() {
    size_t i = (size_t)blockIdx.x * blockDim.x + threadIdx.x;
    const size_t ns = (size_t)N_NODES * N_REL * HID;
    if (i < ns) g_S[i] = 0.0f;
    if (i < (size_t)N_NODES * N_REL) g_cnt[i] = 0.0f;
    if (i < N_GRAPHS * HID) g_pool[i] = 0.0f;
}

// ---------------- build concatenated weight matrix [500, 256] --------------
__global__ void buildW_kernel(const float* __restrict__ W_rel,
                              const float* __restrict__ W_root) {
    int idx = blockIdx.x * blockDim.x + threadIdx.x;
    if (idx >= IN_DIM * NCOL) return;
    int k = idx / NCOL;
    int c = idx % NCOL;
    float v;
    if (c < HID) {
        v = W_root[k * HID + c];
    } else {
        int r = (c - HID) / HID;
        int j = c & (HID - 1);
        v = W_rel[((size_t)r * IN_DIM + k) * HID + j];
    }
    g_W[idx] = v;
}

// ---------------- SGEMM: g_H = node_x[100000,500] @ g_W[500,256] -----------
// 64x64 tile, BK=20 (500 = 25*20 exact), 256 threads, 4x4 micro-tile.
__global__ void __launch_bounds__(256) gemm_kernel(const float* __restrict__ A) {
    __shared__ float As[20][64];  // [k][m] (A transposed in smem)
    __shared__ float Bs[20][64];  // [k][n]
    const int bm = blockIdx.x * 64;
    const int bn = blockIdx.y * 64;
    const int tid = threadIdx.x;
    const int tx = tid & 15;       // n direction (16)
    const int ty = tid >> 4;       // m direction (16)
    float acc[4][4] = {};

    for (int kt = 0; kt < IN_DIM; kt += 20) {
        #pragma unroll
        for (int i = 0; i < 5; i++) {
            int idx = tid + i * 256;       // 1280 = 64*20
            int m = idx / 20, k = idx % 20;
            int gm = bm + m;
            As[k][m] = (gm < N_NODES) ? A[(size_t)gm * IN_DIM + kt + k] : 0.0f;
        }
        #pragma unroll
        for (int i = 0; i < 5; i++) {
            int idx = tid + i * 256;       // 1280 = 20*64
            int k = idx >> 6, n = idx & 63;
            Bs[k][n] = g_W[(kt + k) * NCOL + bn + n];
        }
        __syncthreads();
        #pragma unroll
        for (int k = 0; k < 20; k++) {
            float4 a4 = *(const float4*)&As[k][ty * 4];
            float4 b4 = *(const float4*)&Bs[k][tx * 4];
            float av[4] = {a4.x, a4.y, a4.z, a4.w};
            float bv[4] = {b4.x, b4.y, b4.z, b4.w};
            #pragma unroll
            for (int i = 0; i < 4; i++)
                #pragma unroll
                for (int j = 0; j < 4; j++)
                    acc[i][j] += av[i] * bv[j];
        }
        __syncthreads();
    }

    #pragma unroll
    for (int i = 0; i < 4; i++) {
        int gm = bm + ty * 4 + i;
        if (gm < N_NODES) {
            float4 v = make_float4(acc[i][0], acc[i][1], acc[i][2], acc[i][3]);
            *(float4*)&g_H[(size_t)gm * NCOL + bn + tx * 4] = v;
        }
    }
}

// ---------------- edge scatter: S[dst,r,:] += H[src, rel slice] ------------
// 8 threads per edge, each handles 4 floats via red.global.add.v4.f32.
// Indices are int32 (harness converts int64 inputs to int32).
__global__ void __launch_bounds__(256) edge_kernel(const int* __restrict__ ei,
                                                   const int* __restrict__ ea) {
    int t = blockIdx.x * blockDim.x + threadIdx.x;
    int e = t >> 3;
    int l = t & 7;
    if (e >= N_EDGES) return;
    int src = ei[e];
    int dst = ei[N_EDGES + e];
    int r   = ea[e];
    // memory-safety guards: wrong assumptions become wrong answers, not crashes
    if ((unsigned)src >= N_NODES || (unsigned)dst >= N_NODES || (unsigned)r >= N_REL) return;
    const float4 v = *(const float4*)&g_H[(size_t)src * NCOL + (r + 1) * HID + l * 4];
    float* sp = &g_S[((size_t)dst * N_REL + r) * HID + l * 4];
    asm volatile("red.global.add.v4.f32 [%0], {%1, %2, %3, %4};"
                 :: "l"(sp), "f"(v.x), "f"(v.y), "f"(v.z), "f"(v.w) : "memory");
    if (l == 0) atomicAdd(&g_cnt[(size_t)dst * N_REL + r], 1.0f);
}

// ---------------- node combine + relu + pool -------------------------------
// One warp per node (lane = hidden channel).
__global__ void __launch_bounds__(256) node_kernel(const int* __restrict__ batch,
                                                   const float* __restrict__ bias) {
    int n = blockIdx.x * 8 + (threadIdx.x >> 5);
    int j = threadIdx.x & 31;
    if (n >= N_NODES) return;
    float v = g_H[(size_t)n * NCOL + j] + bias[j];
    #pragma unroll
    for (int r = 0; r < N_REL; r++) {
        float c = g_cnt[(size_t)n * N_REL + r];
        float s = g_S[((size_t)n * N_REL + r) * HID + j];
        v += s / fmaxf(c, 1.0f);
    }
    v = fmaxf(v, 0.0f);
    int g = batch[n];
    if ((unsigned)g >= N_GRAPHS) return;  // memory-safety guard
    atomicAdd(&g_pool[g * HID + j], v);
}

// ---------------- final: out[16,4] = pool[16,32] @ fc_w[32,4] + fc_b -------
__global__ void final_kernel(const float* __restrict__ fc_w,
                             const float* __restrict__ fc_b,
                             float* __restrict__ out) {
    int t = threadIdx.x;
    if (t >= N_GRAPHS * OUT_DIM) return;
    int g = t / OUT_DIM, o = t % OUT_DIM;
    float s = fc_b[o];
    #pragma unroll
    for (int h = 0; h < HID; h++)
        s += g_pool[g * HID + h] * fc_w[h * OUT_DIM + o];
    out[t] = s;
}

// ---------------- launch ----------------------------------------------------
// Inputs resolved by ELEMENT COUNT (all nine are pairwise-distinct), robust to
// metadata ordering. Integer tensors are int32 on device (harness converts
// int64 -> int32; stub documents only float32/int32/bf16 casts).
extern "C" void kernel_launch(void* const* d_in, const int* in_sizes, int n_in,
                              void* d_out, int out_size) {
    const float* node_x     = 0;  // 50,000,000
    const int*   edge_index = 0;  //  3,200,000
    const int*   edge_attr  = 0;  //  1,600,000
    const int*   batch      = 0;  //    100,000
    const float* W_rel      = 0;  //    112,000
    const float* W_root     = 0;  //     16,000
    const float* bias       = 0;  //         32
    const float* fc_w       = 0;  //        128
    const float* fc_b       = 0;  //          4

    for (int i = 0; i < n_in; i++) {
        switch (in_sizes[i]) {
            case 50000000: node_x     = (const float*)d_in[i]; break;
            case  3200000: edge_index = (const int*)d_in[i];   break;
            case  1600000: edge_attr  = (const int*)d_in[i];   break;
            case   100000: batch      = (const int*)d_in[i];   break;
            case   112000: W_rel      = (const float*)d_in[i]; break;
            case    16000: W_root     = (const float*)d_in[i]; break;
            case       32: bias       = (const float*)d_in[i]; break;
            case      128: fc_w       = (const float*)d_in[i]; break;
            case        4: fc_b       = (const float*)d_in[i]; break;
            default: break;
        }
    }
    float* out = (float*)d_out;

    const size_t zero_total = (size_t)N_NODES * N_REL * HID;  // largest zeroed buffer
    zero_kernel<<<(int)((zero_total + 255) / 256), 256>>>();
    buildW_kernel<<<(IN_DIM * NCOL + 255) / 256, 256>>>(W_rel, W_root);

    dim3 gemm_grid((N_NODES + 63) / 64, NCOL / 64);
    gemm_kernel<<<gemm_grid, 256>>>(node_x);

    edge_kernel<<<(N_EDGES * 8) / 256, 256>>>(edge_index, edge_attr);
    node_kernel<<<N_NODES / 8, 256>>>(batch, bias);
    final_kernel<<<1, 64>>>(fc_w, fc_b, out);
}

// round 6
// speedup vs baseline: 1.6576x; 1.6576x over previous
#include <cuda_runtime.h>
#include <cuda_bf16.h>
#include <cstdint>

#define N_NODES  100000
#define N_EDGES  1600000
#define IN_DIM   500
#define KPAD     512
#define HID      32
#define N_REL    7
#define OUT_DIM  4
#define N_GRAPHS 16
#define NCOL     256   // 32 root cols + 7*32 relation cols

// GEMM tiling
#define BM 128
#define BN 64
#define BK 32
#define PITCH 40       // smem row pitch in bf16 elements (80B): conflict-free for ldmatrix

// ---------------- scratch (device globals: allocation-free) ----------------
__device__ float g_H[(size_t)N_NODES * NCOL];          // 102.4 MB
__device__ float g_S[(size_t)N_NODES * N_REL * HID];   // 89.6 MB
__device__ float g_cnt[(size_t)N_NODES * N_REL];       // 2.8 MB
__device__ float g_pool[N_GRAPHS * HID];
__device__ __nv_bfloat16 g_WhT[NCOL * KPAD];           // W^T hi, [n][k] bf16
__device__ __nv_bfloat16 g_WlT[NCOL * KPAD];           // W^T lo

// ---------------- zero scratch -------------------------------------------
__global__ void zero_kernel() {
    size_t i = (size_t)blockIdx.x * blockDim.x + threadIdx.x;
    const size_t ns = (size_t)N_NODES * N_REL * HID;
    if (i < ns) g_S[i] = 0.0f;
    if (i < (size_t)N_NODES * N_REL) g_cnt[i] = 0.0f;
    if (i < N_GRAPHS * HID) g_pool[i] = 0.0f;
}

// ---------------- build transposed, hi/lo-split weights [256][512] --------
__global__ void buildW_kernel(const float* __restrict__ W_rel,
                              const float* __restrict__ W_root) {
    int idx = blockIdx.x * blockDim.x + threadIdx.x;   // over 256*512
    if (idx >= NCOL * KPAD) return;
    int n = idx / KPAD;
    int k = idx % KPAD;
    float w = 0.0f;
    if (k < IN_DIM) {
        if (n < HID) w = W_root[k * HID + n];
        else {
            int r = (n - HID) / HID;
            int j = n & (HID - 1);
            w = W_rel[((size_t)r * IN_DIM + k) * HID + j];
        }
    }
    __nv_bfloat16 hi = __float2bfloat16(w);
    __nv_bfloat16 lo = __float2bfloat16(w - __bfloat162float(hi));
    g_WhT[idx] = hi;
    g_WlT[idx] = lo;
}

// ---------------- tensor-core GEMM: g_H = A[100000,500] @ W[500,256] ------
// bf16 hi/lo split: acc = Ah*Wh + Ah*Wl + Al*Wh  (fp32 accumulate)
__device__ __forceinline__ void mma_bf16(float* c, const uint32_t* a, const uint32_t* b) {
    asm volatile(
        "mma.sync.aligned.m16n8k16.row.col.f32.bf16.bf16.f32 "
        "{%0,%1,%2,%3}, {%4,%5,%6,%7}, {%8,%9}, {%0,%1,%2,%3};"
        : "+f"(c[0]), "+f"(c[1]), "+f"(c[2]), "+f"(c[3])
        : "r"(a[0]), "r"(a[1]), "r"(a[2]), "r"(a[3]), "r"(b[0]), "r"(b[1]));
}
__device__ __forceinline__ void ldm_x4(uint32_t* r, uint32_t addr) {
    asm volatile("ldmatrix.sync.aligned.m8n8.x4.shared.b16 {%0,%1,%2,%3}, [%4];"
                 : "=r"(r[0]), "=r"(r[1]), "=r"(r[2]), "=r"(r[3]) : "r"(addr));
}

__global__ void __launch_bounds__(256) gemm_kernel(const float* __restrict__ A) {
    __shared__ __nv_bfloat16 As_hi[BM][PITCH];
    __shared__ __nv_bfloat16 As_lo[BM][PITCH];
    __shared__ __nv_bfloat16 Bs_hi[BN][PITCH];
    __shared__ __nv_bfloat16 Bs_lo[BN][PITCH];

    const int tid  = threadIdx.x;
    const int lane = tid & 31;
    const int wid  = tid >> 5;
    const int wm   = wid & 3;            // warp row (4 x 32 rows)
    const int wn   = wid >> 2;           // warp col (2 x 32 cols)
    const int bm   = blockIdx.y * BM;    // m-blocks on y
    const int bn   = blockIdx.x * BN;    // n-blocks on x (fast -> A tile L2 reuse)

    float acc[2][4][4];
    #pragma unroll
    for (int i = 0; i < 2; i++)
        #pragma unroll
        for (int j = 0; j < 4; j++)
            #pragma unroll
            for (int q = 0; q < 4; q++) acc[i][j][q] = 0.0f;

    // precompute ldmatrix shared addresses (base row/col per lane)
    const uint32_t as_hi_base = (uint32_t)__cvta_generic_to_shared(&As_hi[0][0]);
    const uint32_t as_lo_base = (uint32_t)__cvta_generic_to_shared(&As_lo[0][0]);
    const uint32_t bs_hi_base = (uint32_t)__cvta_generic_to_shared(&Bs_hi[0][0]);
    const uint32_t bs_lo_base = (uint32_t)__cvta_generic_to_shared(&Bs_lo[0][0]);
    const int a_row  = wm * 32 + (lane & 15);          // + mi*16
    const int a_coff = (lane >> 4) * 16;               // byte offset within k16
    const int b_row  = wn * 32 + (lane & 7) + ((lane & 16) >> 1);  // + ntile*16
    const int b_coff = ((lane >> 3) & 1) * 16;

    for (int kt = 0; kt < KPAD; kt += BK) {
        // ---- load A tile [BM x BK] fp32 -> hi/lo bf16 smem ----
        #pragma unroll
        for (int i = 0; i < 4; i++) {
            int idx = i * 256 + tid;       // 1024 float4 slots
            int row = idx >> 3;
            int c4  = idx & 7;
            int gm  = bm + row;
            if (gm >= N_NODES) gm = N_NODES - 1;   // clamp: values unused (store guarded)
            float4 v;
            int k0 = kt + c4 * 4;
            if (k0 + 3 < IN_DIM) {
                v = *(const float4*)&A[(size_t)gm * IN_DIM + k0];
            } else {
                v.x = (k0 + 0 < IN_DIM) ? A[(size_t)gm * IN_DIM + k0 + 0] : 0.0f;
                v.y = (k0 + 1 < IN_DIM) ? A[(size_t)gm * IN_DIM + k0 + 1] : 0.0f;
                v.z = (k0 + 2 < IN_DIM) ? A[(size_t)gm * IN_DIM + k0 + 2] : 0.0f;
                v.w = (k0 + 3 < IN_DIM) ? A[(size_t)gm * IN_DIM + k0 + 3] : 0.0f;
            }
            float f[4] = {v.x, v.y, v.z, v.w};
            __nv_bfloat16 hi[4], lo[4];
            #pragma unroll
            for (int j = 0; j < 4; j++) {
                hi[j] = __float2bfloat16(f[j]);
                lo[j] = __float2bfloat16(f[j] - __bfloat162float(hi[j]));
            }
            *(uint2*)&As_hi[row][c4 * 4] = *(uint2*)hi;
            *(uint2*)&As_lo[row][c4 * 4] = *(uint2*)lo;
        }
        // ---- load B tiles [BN x BK] bf16 (pre-split, pre-transposed) ----
        {
            int n = tid >> 2;
            int q = tid & 3;
            *(uint4*)&Bs_hi[n][q * 8] = *(const uint4*)&g_WhT[(size_t)(bn + n) * KPAD + kt + q * 8];
            *(uint4*)&Bs_lo[n][q * 8] = *(const uint4*)&g_WlT[(size_t)(bn + n) * KPAD + kt + q * 8];
        }
        __syncthreads();

        // ---- 2 k16 steps ----
        #pragma unroll
        for (int ks = 0; ks < 2; ks++) {
            const int kb = ks * 16 * 2;   // byte offset of k16 step
            uint32_t ah[2][4], al[2][4];
            #pragma unroll
            for (int mi = 0; mi < 2; mi++) {
                uint32_t off = (uint32_t)((a_row + mi * 16) * (PITCH * 2)) + kb + a_coff;
                ldm_x4(ah[mi], as_hi_base + off);
                ldm_x4(al[mi], as_lo_base + off);
            }
            uint32_t bh[2][4], bl[2][4];   // each x4 covers 2 n-tiles
            #pragma unroll
            for (int nt = 0; nt < 2; nt++) {
                uint32_t off = (uint32_t)((b_row + nt * 16) * (PITCH * 2)) + kb + b_coff;
                ldm_x4(bh[nt], bs_hi_base + off);
                ldm_x4(bl[nt], bs_lo_base + off);
            }
            #pragma unroll
            for (int mi = 0; mi < 2; mi++) {
                #pragma unroll
                for (int ni = 0; ni < 4; ni++) {
                    const uint32_t* bhp = &bh[ni >> 1][(ni & 1) * 2];
                    const uint32_t* blp = &bl[ni >> 1][(ni & 1) * 2];
                    mma_bf16(acc[mi][ni], ah[mi], bhp);   // Ah * Wh
                    mma_bf16(acc[mi][ni], ah[mi], blp);   // Ah * Wl
                    mma_bf16(acc[mi][ni], al[mi], bhp);   // Al * Wh
                }
            }
        }
        __syncthreads();
    }

    // ---- epilogue: store to g_H ----
    #pragma unroll
    for (int mi = 0; mi < 2; mi++) {
        #pragma unroll
        for (int ni = 0; ni < 4; ni++) {
            int col = bn + wn * 32 + ni * 8 + (lane & 3) * 2;
            int r0  = bm + wm * 32 + mi * 16 + (lane >> 2);
            if (r0 < N_NODES)
                *(float2*)&g_H[(size_t)r0 * NCOL + col] = make_float2(acc[mi][ni][0], acc[mi][ni][1]);
            int r1 = r0 + 8;
            if (r1 < N_NODES)
                *(float2*)&g_H[(size_t)r1 * NCOL + col] = make_float2(acc[mi][ni][2], acc[mi][ni][3]);
        }
    }
}

// ---------------- edge scatter: S[dst,r,:] += H[src, rel slice] ------------
__global__ void __launch_bounds__(256) edge_kernel(const int* __restrict__ ei,
                                                   const int* __restrict__ ea) {
    int t = blockIdx.x * blockDim.x + threadIdx.x;
    int e = t >> 3;
    int l = t & 7;
    if (e >= N_EDGES) return;
    int src = ei[e];
    int dst = ei[N_EDGES + e];
    int r   = ea[e];
    if ((unsigned)src >= N_NODES || (unsigned)dst >= N_NODES || (unsigned)r >= N_REL) return;
    const float4 v = *(const float4*)&g_H[(size_t)src * NCOL + (r + 1) * HID + l * 4];
    float* sp = &g_S[((size_t)dst * N_REL + r) * HID + l * 4];
    asm volatile("red.global.add.v4.f32 [%0], {%1, %2, %3, %4};"
                 :: "l"(sp), "f"(v.x), "f"(v.y), "f"(v.z), "f"(v.w) : "memory");
    if (l == 0) atomicAdd(&g_cnt[(size_t)dst * N_REL + r], 1.0f);
}

// ---------------- node combine + relu + pool -------------------------------
__global__ void __launch_bounds__(256) node_kernel(const int* __restrict__ batch,
                                                   const float* __restrict__ bias) {
    int n = blockIdx.x * 8 + (threadIdx.x >> 5);
    int j = threadIdx.x & 31;
    if (n >= N_NODES) return;
    float v = g_H[(size_t)n * NCOL + j] + bias[j];
    #pragma unroll
    for (int r = 0; r < N_REL; r++) {
        float c = g_cnt[(size_t)n * N_REL + r];
        float s = g_S[((size_t)n * N_REL + r) * HID + j];
        v += s / fmaxf(c, 1.0f);
    }
    v = fmaxf(v, 0.0f);
    int g = batch[n];
    if ((unsigned)g >= N_GRAPHS) return;
    atomicAdd(&g_pool[g * HID + j], v);
}

// ---------------- final: out[16,4] = pool[16,32] @ fc_w[32,4] + fc_b -------
__global__ void final_kernel(const float* __restrict__ fc_w,
                             const float* __restrict__ fc_b,
                             float* __restrict__ out) {
    int t = threadIdx.x;
    if (t >= N_GRAPHS * OUT_DIM) return;
    int g = t / OUT_DIM, o = t % OUT_DIM;
    float s = fc_b[o];
    #pragma unroll
    for (int h = 0; h < HID; h++)
        s += g_pool[g * HID + h] * fc_w[h * OUT_DIM + o];
    out[t] = s;
}

// ---------------- launch ----------------------------------------------------
extern "C" void kernel_launch(void* const* d_in, const int* in_sizes, int n_in,
                              void* d_out, int out_size) {
    const float* node_x     = 0;  // 50,000,000
    const int*   edge_index = 0;  //  3,200,000
    const int*   edge_attr  = 0;  //  1,600,000
    const int*   batch      = 0;  //    100,000
    const float* W_rel      = 0;  //    112,000
    const float* W_root     = 0;  //     16,000
    const float* bias       = 0;  //         32
    const float* fc_w       = 0;  //        128
    const float* fc_b       = 0;  //          4

    for (int i = 0; i < n_in; i++) {
        switch (in_sizes[i]) {
            case 50000000: node_x     = (const float*)d_in[i]; break;
            case  3200000: edge_index = (const int*)d_in[i];   break;
            case  1600000: edge_attr  = (const int*)d_in[i];   break;
            case   100000: batch      = (const int*)d_in[i];   break;
            case   112000: W_rel      = (const float*)d_in[i]; break;
            case    16000: W_root     = (const float*)d_in[i]; break;
            case       32: bias       = (const float*)d_in[i]; break;
            case      128: fc_w       = (const float*)d_in[i]; break;
            case        4: fc_b       = (const float*)d_in[i]; break;
            default: break;
        }
    }
    float* out = (float*)d_out;

    const size_t zero_total = (size_t)N_NODES * N_REL * HID;
    zero_kernel<<<(int)((zero_total + 255) / 256), 256>>>();
    buildW_kernel<<<(NCOL * KPAD + 255) / 256, 256>>>(W_rel, W_root);

    dim3 gemm_grid(NCOL / BN, (N_NODES + BM - 1) / BM);   // (4, 782), bn fast
    gemm_kernel<<<gemm_grid, 256>>>(node_x);

    edge_kernel<<<(N_EDGES * 8) / 256, 256>>>(edge_index, edge_attr);
    node_kernel<<<N_NODES / 8, 256>>>(batch, bias);
    final_kernel<<<1, 64>>>(fc_w, fc_b, out);
}

// round 7
// speedup vs baseline: 2.7569x; 1.6631x over previous
#include <cuda_runtime.h>
#include <cuda_bf16.h>
#include <cstdint>

#define N_NODES  100000
#define N_EDGES  1600000
#define IN_DIM   500
#define KPAD     512
#define HID      32
#define N_REL    7
#define OUT_DIM  4
#define N_GRAPHS 16
#define NCOL     256   // 32 root cols + 7*32 relation cols

// GEMM tiling: full output width per block -> A tile loaded exactly once
#define BM 64
#define BN 256
#define BK 32
#define PITCH 40       // smem row pitch in bf16 (80B): conflict-free for ldmatrix

// ---------------- scratch (device globals: allocation-free) ----------------
__device__ float g_H[(size_t)N_NODES * NCOL];          // 102.4 MB
__device__ float g_S[(size_t)N_NODES * N_REL * HID];   // 89.6 MB
__device__ float g_cnt[(size_t)N_NODES * N_REL];       // 2.8 MB
__device__ float g_pool[N_GRAPHS * HID];
__device__ __nv_bfloat16 g_WT[NCOL * KPAD];            // W^T bf16, [n][k]

// ---------------- zero scratch -------------------------------------------
__global__ void zero_kernel() {
    size_t i = (size_t)blockIdx.x * blockDim.x + threadIdx.x;
    const size_t ns = (size_t)N_NODES * N_REL * HID;
    if (i < ns) g_S[i] = 0.0f;
    if (i < (size_t)N_NODES * N_REL) g_cnt[i] = 0.0f;
    if (i < N_GRAPHS * HID) g_pool[i] = 0.0f;
}

// ---------------- build transposed bf16 weights [256][512] ----------------
__global__ void buildW_kernel(const float* __restrict__ W_rel,
                              const float* __restrict__ W_root) {
    int idx = blockIdx.x * blockDim.x + threadIdx.x;   // over 256*512
    if (idx >= NCOL * KPAD) return;
    int n = idx / KPAD;
    int k = idx % KPAD;
    float w = 0.0f;
    if (k < IN_DIM) {
        if (n < HID) w = W_root[k * HID + n];
        else {
            int r = (n - HID) / HID;
            int j = n & (HID - 1);
            w = W_rel[((size_t)r * IN_DIM + k) * HID + j];
        }
    }
    g_WT[idx] = __float2bfloat16(w);
}

// ---------------- tensor-core GEMM: g_H = A[100000,500] @ W[500,256] ------
__device__ __forceinline__ void mma_bf16(float* c, const uint32_t* a, const uint32_t* b) {
    asm volatile(
        "mma.sync.aligned.m16n8k16.row.col.f32.bf16.bf16.f32 "
        "{%0,%1,%2,%3}, {%4,%5,%6,%7}, {%8,%9}, {%0,%1,%2,%3};"
        : "+f"(c[0]), "+f"(c[1]), "+f"(c[2]), "+f"(c[3])
        : "r"(a[0]), "r"(a[1]), "r"(a[2]), "r"(a[3]), "r"(b[0]), "r"(b[1]));
}
__device__ __forceinline__ void ldm_x4(uint32_t* r, uint32_t addr) {
    asm volatile("ldmatrix.sync.aligned.m8n8.x4.shared.b16 {%0,%1,%2,%3}, [%4];"
                 : "=r"(r[0]), "=r"(r[1]), "=r"(r[2]), "=r"(r[3]) : "r"(addr));
}

__global__ void __launch_bounds__(256, 2) gemm_kernel(const float* __restrict__ A) {
    __shared__ __nv_bfloat16 As[BM][PITCH];   // 5.1 KB
    __shared__ __nv_bfloat16 Bs[BN][PITCH];   // 20.5 KB

    const int tid  = threadIdx.x;
    const int lane = tid & 31;
    const int wid  = tid >> 5;
    const int wm   = wid & 1;            // 2 warp rows  x 32 rows
    const int wn   = wid >> 1;           // 4 warp cols  x 64 cols
    const int bm   = blockIdx.x * BM;

    float acc[2][8][4];
    #pragma unroll
    for (int i = 0; i < 2; i++)
        #pragma unroll
        for (int j = 0; j < 8; j++)
            #pragma unroll
            for (int q = 0; q < 4; q++) acc[i][j][q] = 0.0f;

    const uint32_t as_base = (uint32_t)__cvta_generic_to_shared(&As[0][0]);
    const uint32_t bs_base = (uint32_t)__cvta_generic_to_shared(&Bs[0][0]);
    const int a_row  = wm * 32 + (lane & 15);                      // + mi*16
    const int a_coff = (lane >> 4) * 16;                           // byte off in k16
    const int b_row  = wn * 64 + (lane & 7) + ((lane & 16) >> 1);  // + bt*16
    const int b_coff = ((lane >> 3) & 1) * 16;

    for (int kt = 0; kt < KPAD; kt += BK) {
        // ---- A tile [BM x BK] fp32 -> bf16 smem (2 float4 per thread) ----
        #pragma unroll
        for (int i = 0; i < 2; i++) {
            int idx = i * 256 + tid;       // 512 float4 slots
            int row = idx >> 3;
            int c4  = idx & 7;
            int gm  = bm + row;
            if (gm >= N_NODES) gm = N_NODES - 1;   // clamp (stores guarded)
            float4 v;
            int k0 = kt + c4 * 4;
            if (k0 + 3 < IN_DIM) {
                v = *(const float4*)&A[(size_t)gm * IN_DIM + k0];
            } else {
                v.x = (k0 + 0 < IN_DIM) ? A[(size_t)gm * IN_DIM + k0 + 0] : 0.0f;
                v.y = (k0 + 1 < IN_DIM) ? A[(size_t)gm * IN_DIM + k0 + 1] : 0.0f;
                v.z = (k0 + 2 < IN_DIM) ? A[(size_t)gm * IN_DIM + k0 + 2] : 0.0f;
                v.w = (k0 + 3 < IN_DIM) ? A[(size_t)gm * IN_DIM + k0 + 3] : 0.0f;
            }
            __nv_bfloat16 h[4] = {__float2bfloat16(v.x), __float2bfloat16(v.y),
                                  __float2bfloat16(v.z), __float2bfloat16(v.w)};
            *(uint2*)&As[row][c4 * 4] = *(uint2*)h;
        }
        // ---- B tile [BN x BK] bf16 from L2-resident g_WT (4 uint4/thread) ----
        #pragma unroll
        for (int i = 0; i < 4; i++) {
            int idx = i * 256 + tid;       // 1024 uint4 slots
            int n = idx >> 2;
            int q = idx & 3;
            *(uint4*)&Bs[n][q * 8] = *(const uint4*)&g_WT[(size_t)n * KPAD + kt + q * 8];
        }
        __syncthreads();

        // ---- 2 k16 steps ----
        #pragma unroll
        for (int ks = 0; ks < 2; ks++) {
            const int kb = ks * 32;        // byte offset of k16 step
            uint32_t ah[2][4];
            #pragma unroll
            for (int mi = 0; mi < 2; mi++)
                ldm_x4(ah[mi], as_base + (uint32_t)((a_row + mi * 16) * (PITCH * 2)) + kb + a_coff);
            uint32_t bh[4][4];             // each x4 covers 2 n8 tiles
            #pragma unroll
            for (int bt = 0; bt < 4; bt++)
                ldm_x4(bh[bt], bs_base + (uint32_t)((b_row + bt * 16) * (PITCH * 2)) + kb + b_coff);
            #pragma unroll
            for (int mi = 0; mi < 2; mi++)
                #pragma unroll
                for (int ni = 0; ni < 8; ni++)
                    mma_bf16(acc[mi][ni], ah[mi], &bh[ni >> 1][(ni & 1) * 2]);
        }
        __syncthreads();
    }

    // ---- epilogue ----
    #pragma unroll
    for (int mi = 0; mi < 2; mi++) {
        #pragma unroll
        for (int ni = 0; ni < 8; ni++) {
            int col = wn * 64 + ni * 8 + (lane & 3) * 2;
            int r0  = bm + wm * 32 + mi * 16 + (lane >> 2);
            if (r0 < N_NODES)
                *(float2*)&g_H[(size_t)r0 * NCOL + col] = make_float2(acc[mi][ni][0], acc[mi][ni][1]);
            int r1 = r0 + 8;
            if (r1 < N_NODES)
                *(float2*)&g_H[(size_t)r1 * NCOL + col] = make_float2(acc[mi][ni][2], acc[mi][ni][3]);
        }
    }
}

// ---------------- edge scatter: S[dst,r,:] += H[src, rel slice] ------------
__global__ void __launch_bounds__(256) edge_kernel(const int* __restrict__ ei,
                                                   const int* __restrict__ ea) {
    int t = blockIdx.x * blockDim.x + threadIdx.x;
    int e = t >> 3;
    int l = t & 7;
    if (e >= N_EDGES) return;
    int src = ei[e];
    int dst = ei[N_EDGES + e];
    int r   = ea[e];
    if ((unsigned)src >= N_NODES || (unsigned)dst >= N_NODES || (unsigned)r >= N_REL) return;
    const float4 v = *(const float4*)&g_H[(size_t)src * NCOL + (r + 1) * HID + l * 4];
    float* sp = &g_S[((size_t)dst * N_REL + r) * HID + l * 4];
    asm volatile("red.global.add.v4.f32 [%0], {%1, %2, %3, %4};"
                 :: "l"(sp), "f"(v.x), "f"(v.y), "f"(v.z), "f"(v.w) : "memory");
    if (l == 0) atomicAdd(&g_cnt[(size_t)dst * N_REL + r], 1.0f);
}

// ---------------- node combine + relu + pool -------------------------------
__global__ void __launch_bounds__(256) node_kernel(const int* __restrict__ batch,
                                                   const float* __restrict__ bias) {
    int n = blockIdx.x * 8 + (threadIdx.x >> 5);
    int j = threadIdx.x & 31;
    if (n >= N_NODES) return;
    float v = g_H[(size_t)n * NCOL + j] + bias[j];
    #pragma unroll
    for (int r = 0; r < N_REL; r++) {
        float c = g_cnt[(size_t)n * N_REL + r];
        float s = g_S[((size_t)n * N_REL + r) * HID + j];
        v += s / fmaxf(c, 1.0f);
    }
    v = fmaxf(v, 0.0f);
    int g = batch[n];
    if ((unsigned)g >= N_GRAPHS) return;
    atomicAdd(&g_pool[g * HID + j], v);
}

// ---------------- final: out[16,4] = pool[16,32] @ fc_w[32,4] + fc_b -------
__global__ void final_kernel(const float* __restrict__ fc_w,
                             const float* __restrict__ fc_b,
                             float* __restrict__ out) {
    int t = threadIdx.x;
    if (t >= N_GRAPHS * OUT_DIM) return;
    int g = t / OUT_DIM, o = t % OUT_DIM;
    float s = fc_b[o];
    #pragma unroll
    for (int h = 0; h < HID; h++)
        s += g_pool[g * HID + h] * fc_w[h * OUT_DIM + o];
    out[t] = s;
}

// ---------------- launch ----------------------------------------------------
extern "C" void kernel_launch(void* const* d_in, const int* in_sizes, int n_in,
                              void* d_out, int out_size) {
    const float* node_x     = 0;  // 50,000,000
    const int*   edge_index = 0;  //  3,200,000
    const int*   edge_attr  = 0;  //  1,600,000
    const int*   batch      = 0;  //    100,000
    const float* W_rel      = 0;  //    112,000
    const float* W_root     = 0;  //     16,000
    const float* bias       = 0;  //         32
    const float* fc_w       = 0;  //        128
    const float* fc_b       = 0;  //          4

    for (int i = 0; i < n_in; i++) {
        switch (in_sizes[i]) {
            case 50000000: node_x     = (const float*)d_in[i]; break;
            case  3200000: edge_index = (const int*)d_in[i];   break;
            case  1600000: edge_attr  = (const int*)d_in[i];   break;
            case   100000: batch      = (const int*)d_in[i];   break;
            case   112000: W_rel      = (const float*)d_in[i]; break;
            case    16000: W_root     = (const float*)d_in[i]; break;
            case       32: bias       = (const float*)d_in[i]; break;
            case      128: fc_w       = (const float*)d_in[i]; break;
            case        4: fc_b       = (const float*)d_in[i]; break;
            default: break;
        }
    }
    float* out = (float*)d_out;

    const size_t zero_total = (size_t)N_NODES * N_REL * HID;
    zero_kernel<<<(int)((zero_total + 255) / 256), 256>>>();
    buildW_kernel<<<(NCOL * KPAD + 255) / 256, 256>>>(W_rel, W_root);

    gemm_kernel<<<(N_NODES + BM - 1) / BM, 256>>>(node_x);

    edge_kernel<<<(N_EDGES * 8) / 256, 256>>>(edge_index, edge_attr);
    node_kernel<<<N_NODES / 8, 256>>>(batch, bias);
    final_kernel<<<1, 64>>>(fc_w, fc_b, out);
}

// round 8
// speedup vs baseline: 3.6438x; 1.3217x over previous
#include <cuda_runtime.h>
#include <cuda_bf16.h>
#include <cstdint>

#define N_NODES  100000
#define N_EDGES  1600000
#define IN_DIM   500
#define KPAD     512
#define HID      32
#define N_REL    7
#define OUT_DIM  4
#define N_GRAPHS 16
#define NCOL     256   // 32 root cols + 7*32 relation cols

// GEMM tiling: full output width per block -> A tile loaded exactly once
#define BM 64
#define BN 256
#define BK 32
#define NITER (KPAD / BK)   // 16
#define PITCH 40            // smem row pitch in bf16 (80B): conflict-free for ldmatrix

// ---------------- scratch (device globals: allocation-free) ----------------
__device__ __nv_bfloat16 g_Hb[(size_t)N_NODES * NCOL]; // 51.2 MB (bf16 H)
__device__ float g_S[(size_t)N_NODES * N_REL * HID];   // 89.6 MB
__device__ float g_cnt[(size_t)N_NODES * N_REL];       // 2.8 MB
__device__ float g_pool[N_GRAPHS * HID];
__device__ __nv_bfloat16 g_WT[NCOL * KPAD];            // W^T bf16, [n][k]

// ---------------- zero scratch (vectorized) --------------------------------
__global__ void zero_kernel() {
    size_t i = (size_t)blockIdx.x * blockDim.x + threadIdx.x;
    const size_t s4 = (size_t)N_NODES * N_REL * HID / 4;   // 5.6M float4
    if (i < s4) ((float4*)g_S)[i] = make_float4(0.f, 0.f, 0.f, 0.f);
    if (i < (size_t)N_NODES * N_REL / 4) ((float4*)g_cnt)[i] = make_float4(0.f, 0.f, 0.f, 0.f);
    if (i < N_GRAPHS * HID) g_pool[i] = 0.0f;
}

// ---------------- build transposed bf16 weights [256][512] ----------------
__global__ void buildW_kernel(const float* __restrict__ W_rel,
                              const float* __restrict__ W_root) {
    int idx = blockIdx.x * blockDim.x + threadIdx.x;
    if (idx >= NCOL * KPAD) return;
    int n = idx / KPAD;
    int k = idx % KPAD;
    float w = 0.0f;
    if (k < IN_DIM) {
        if (n < HID) w = W_root[k * HID + n];
        else {
            int r = (n - HID) / HID;
            int j = n & (HID - 1);
            w = W_rel[((size_t)r * IN_DIM + k) * HID + j];
        }
    }
    g_WT[idx] = __float2bfloat16(w);
}

// ---------------- tensor-core GEMM (2-stage pipelined) ---------------------
__device__ __forceinline__ void mma_bf16(float* c, const uint32_t* a, const uint32_t* b) {
    asm volatile(
        "mma.sync.aligned.m16n8k16.row.col.f32.bf16.bf16.f32 "
        "{%0,%1,%2,%3}, {%4,%5,%6,%7}, {%8,%9}, {%0,%1,%2,%3};"
        : "+f"(c[0]), "+f"(c[1]), "+f"(c[2]), "+f"(c[3])
        : "r"(a[0]), "r"(a[1]), "r"(a[2]), "r"(a[3]), "r"(b[0]), "r"(b[1]));
}
__device__ __forceinline__ void ldm_x4(uint32_t* r, uint32_t addr) {
    asm volatile("ldmatrix.sync.aligned.m8n8.x4.shared.b16 {%0,%1,%2,%3}, [%4];"
                 : "=r"(r[0]), "=r"(r[1]), "=r"(r[2]), "=r"(r[3]) : "r"(addr));
}
__device__ __forceinline__ void cp_async16(uint32_t dst, const void* src) {
    asm volatile("cp.async.cg.shared.global [%0], [%1], 16;" :: "r"(dst), "l"(src));
}

// dynamic smem layout (bf16 elems): As[2][BM][PITCH] then Bs[2][BN][PITCH]
#define AS_ELEMS (BM * PITCH)          // 2560
#define BS_ELEMS (BN * PITCH)          // 10240
#define BS_BASE  (2 * AS_ELEMS)        // 5120
#define SMEM_BYTES ((2 * AS_ELEMS + 2 * BS_ELEMS) * 2)   // 51200

__global__ void __launch_bounds__(256, 2) gemm_kernel(const float* __restrict__ A) {
    extern __shared__ __nv_bfloat16 sm[];

    const int tid  = threadIdx.x;
    const int lane = tid & 31;
    const int wid  = tid >> 5;
    const int wm   = wid & 1;            // 2 warp rows x 32
    const int wn   = wid >> 1;           // 4 warp cols x 64
    const int bm   = blockIdx.x * BM;

    float acc[2][8][4];
    #pragma unroll
    for (int i = 0; i < 2; i++)
        #pragma unroll
        for (int j = 0; j < 8; j++)
            #pragma unroll
            for (int q = 0; q < 4; q++) acc[i][j][q] = 0.0f;

    const uint32_t sm_base = (uint32_t)__cvta_generic_to_shared(sm);
    // A load indexing (2 float4 per thread per stage)
    const int ar0 = tid >> 3;            // rows tid/8 and +32
    const int ac4 = tid & 7;
    int gm0 = bm + ar0;      if (gm0 >= N_NODES) gm0 = N_NODES - 1;
    int gm1 = bm + ar0 + 32; if (gm1 >= N_NODES) gm1 = N_NODES - 1;
    const float* aptr0 = A + (size_t)gm0 * IN_DIM + ac4 * 4;
    const float* aptr1 = A + (size_t)gm1 * IN_DIM + ac4 * 4;
    // B cp.async indexing (4 x 16B per thread per stage)
    const int bn_row = tid >> 2;          // rows tid/4, +64, +128, +192
    const int bq     = tid & 3;

    // ldmatrix lane addressing
    const int a_row  = wm * 32 + (lane & 15);
    const int a_coff = (lane >> 4) * 16;
    const int b_row  = wn * 64 + (lane & 7) + ((lane & 16) >> 1);
    const int b_coff = ((lane >> 3) & 1) * 16;

    float4 areg0, areg1;

    // ---- helper lambdas (inlined) ----
    auto issue_B = [&](int stage, int kt) {
        uint32_t dst = sm_base + (uint32_t)(BS_BASE + stage * BS_ELEMS) * 2;
        #pragma unroll
        for (int i = 0; i < 4; i++) {
            int n = bn_row + i * 64;
            cp_async16(dst + (uint32_t)(n * PITCH + bq * 8) * 2,
                       &g_WT[(size_t)n * KPAD + kt + bq * 8]);
        }
        asm volatile("cp.async.commit_group;");
    };
    auto issue_A = [&](int kt) {
        // IN_DIM=500: last tile (kt=480) columns 500..511 must be zero
        if (kt + ac4 * 4 + 3 < IN_DIM) {
            areg0 = *(const float4*)(aptr0 + kt);
            areg1 = *(const float4*)(aptr1 + kt);
        } else {
            const float* p0 = aptr0 + kt;
            const float* p1 = aptr1 + kt;
            int k0 = kt + ac4 * 4;
            areg0.x = (k0 + 0 < IN_DIM) ? p0[0] : 0.f;
            areg0.y = (k0 + 1 < IN_DIM) ? p0[1] : 0.f;
            areg0.z = (k0 + 2 < IN_DIM) ? p0[2] : 0.f;
            areg0.w = (k0 + 3 < IN_DIM) ? p0[3] : 0.f;
            areg1.x = (k0 + 0 < IN_DIM) ? p1[0] : 0.f;
            areg1.y = (k0 + 1 < IN_DIM) ? p1[1] : 0.f;
            areg1.z = (k0 + 2 < IN_DIM) ? p1[2] : 0.f;
            areg1.w = (k0 + 3 < IN_DIM) ? p1[3] : 0.f;
        }
    };
    auto store_A = [&](int stage) {
        __nv_bfloat16* as = sm + stage * AS_ELEMS;
        __nv_bfloat16 h0[4] = {__float2bfloat16(areg0.x), __float2bfloat16(areg0.y),
                               __float2bfloat16(areg0.z), __float2bfloat16(areg0.w)};
        __nv_bfloat16 h1[4] = {__float2bfloat16(areg1.x), __float2bfloat16(areg1.y),
                               __float2bfloat16(areg1.z), __float2bfloat16(areg1.w)};
        *(uint2*)&as[ar0 * PITCH + ac4 * 4]        = *(uint2*)h0;
        *(uint2*)&as[(ar0 + 32) * PITCH + ac4 * 4] = *(uint2*)h1;
    };

    // ---- prologue: fill stage 0 ----
    issue_B(0, 0);
    issue_A(0);
    store_A(0);
    asm volatile("cp.async.wait_group 0;");
    __syncthreads();

    // ---- main loop ----
    for (int it = 0; it < NITER; it++) {
        const int cur = it & 1;
        const int nxt = cur ^ 1;
        if (it + 1 < NITER) {
            issue_B(nxt, (it + 1) * BK);
            issue_A((it + 1) * BK);
        }

        const uint32_t as_st = sm_base + (uint32_t)(cur * AS_ELEMS) * 2;
        const uint32_t bs_st = sm_base + (uint32_t)(BS_BASE + cur * BS_ELEMS) * 2;
        #pragma unroll
        for (int ks = 0; ks < 2; ks++) {
            const int kb = ks * 32;   // byte offset of k16 step
            uint32_t ah[2][4];
            #pragma unroll
            for (int mi = 0; mi < 2; mi++)
                ldm_x4(ah[mi], as_st + (uint32_t)((a_row + mi * 16) * (PITCH * 2)) + kb + a_coff);
            uint32_t bh[4][4];
            #pragma unroll
            for (int bt = 0; bt < 4; bt++)
                ldm_x4(bh[bt], bs_st + (uint32_t)((b_row + bt * 16) * (PITCH * 2)) + kb + b_coff);
            #pragma unroll
            for (int mi = 0; mi < 2; mi++)
                #pragma unroll
                for (int ni = 0; ni < 8; ni++)
                    mma_bf16(acc[mi][ni], ah[mi], &bh[ni >> 1][(ni & 1) * 2]);
        }

        if (it + 1 < NITER) {
            store_A(nxt);
            asm volatile("cp.async.wait_group 0;");
        }
        __syncthreads();
    }

    // ---- epilogue: store bf16 H ----
    #pragma unroll
    for (int mi = 0; mi < 2; mi++) {
        #pragma unroll
        for (int ni = 0; ni < 8; ni++) {
            int col = wn * 64 + ni * 8 + (lane & 3) * 2;
            int r0  = bm + wm * 32 + mi * 16 + (lane >> 2);
            __nv_bfloat162 v01 = __floats2bfloat162_rn(acc[mi][ni][0], acc[mi][ni][1]);
            __nv_bfloat162 v23 = __floats2bfloat162_rn(acc[mi][ni][2], acc[mi][ni][3]);
            if (r0 < N_NODES)
                *(__nv_bfloat162*)&g_Hb[(size_t)r0 * NCOL + col] = v01;
            if (r0 + 8 < N_NODES)
                *(__nv_bfloat162*)&g_Hb[(size_t)(r0 + 8) * NCOL + col] = v23;
        }
    }
}

// ---------------- edge scatter: S[dst,r,:] += H[src, rel slice] ------------
// 8 threads/edge, each converts 4 bf16 -> fp32 and REDG.v4 into g_S.
__global__ void __launch_bounds__(256) edge_kernel(const int* __restrict__ ei,
                                                   const int* __restrict__ ea) {
    int t = blockIdx.x * blockDim.x + threadIdx.x;
    int e = t >> 3;
    int l = t & 7;
    if (e >= N_EDGES) return;
    int src = ei[e];
    int dst = ei[N_EDGES + e];
    int r   = ea[e];
    if ((unsigned)src >= N_NODES || (unsigned)dst >= N_NODES || (unsigned)r >= N_REL) return;
    const __nv_bfloat162* hp =
        (const __nv_bfloat162*)&g_Hb[(size_t)src * NCOL + (r + 1) * HID + l * 4];
    float2 f0 = __bfloat1622float2(hp[0]);
    float2 f1 = __bfloat1622float2(hp[1]);
    float* sp = &g_S[((size_t)dst * N_REL + r) * HID + l * 4];
    asm volatile("red.global.add.v4.f32 [%0], {%1, %2, %3, %4};"
                 :: "l"(sp), "f"(f0.x), "f"(f0.y), "f"(f1.x), "f"(f1.y) : "memory");
    if (l == 0) atomicAdd(&g_cnt[(size_t)dst * N_REL + r], 1.0f);
}

// ---------------- node combine + relu + pool -------------------------------
__global__ void __launch_bounds__(256) node_kernel(const int* __restrict__ batch,
                                                   const float* __restrict__ bias) {
    int n = blockIdx.x * 8 + (threadIdx.x >> 5);
    int j = threadIdx.x & 31;
    if (n >= N_NODES) return;
    float v = __bfloat162float(g_Hb[(size_t)n * NCOL + j]) + bias[j];
    #pragma unroll
    for (int r = 0; r < N_REL; r++) {
        float c = g_cnt[(size_t)n * N_REL + r];
        float s = g_S[((size_t)n * N_REL + r) * HID + j];
        v += s / fmaxf(c, 1.0f);
    }
    v = fmaxf(v, 0.0f);
    int g = batch[n];
    if ((unsigned)g >= N_GRAPHS) return;
    atomicAdd(&g_pool[g * HID + j], v);
}

// ---------------- final: out[16,4] = pool[16,32] @ fc_w[32,4] + fc_b -------
__global__ void final_kernel(const float* __restrict__ fc_w,
                             const float* __restrict__ fc_b,
                             float* __restrict__ out) {
    int t = threadIdx.x;
    if (t >= N_GRAPHS * OUT_DIM) return;
    int g = t / OUT_DIM, o = t % OUT_DIM;
    float s = fc_b[o];
    #pragma unroll
    for (int h = 0; h < HID; h++)
        s += g_pool[g * HID + h] * fc_w[h * OUT_DIM + o];
    out[t] = s;
}

// ---------------- launch ----------------------------------------------------
extern "C" void kernel_launch(void* const* d_in, const int* in_sizes, int n_in,
                              void* d_out, int out_size) {
    const float* node_x     = 0;  // 50,000,000
    const int*   edge_index = 0;  //  3,200,000
    const int*   edge_attr  = 0;  //  1,600,000
    const int*   batch      = 0;  //    100,000
    const float* W_rel      = 0;  //    112,000
    const float* W_root     = 0;  //     16,000
    const float* bias       = 0;  //         32
    const float* fc_w       = 0;  //        128
    const float* fc_b       = 0;  //          4

    for (int i = 0; i < n_in; i++) {
        switch (in_sizes[i]) {
            case 50000000: node_x     = (const float*)d_in[i]; break;
            case  3200000: edge_index = (const int*)d_in[i];   break;
            case  1600000: edge_attr  = (const int*)d_in[i];   break;
            case   100000: batch      = (const int*)d_in[i];   break;
            case   112000: W_rel      = (const float*)d_in[i]; break;
            case    16000: W_root     = (const float*)d_in[i]; break;
            case       32: bias       = (const float*)d_in[i]; break;
            case      128: fc_w       = (const float*)d_in[i]; break;
            case        4: fc_b       = (const float*)d_in[i]; break;
            default: break;
        }
    }
    float* out = (float*)d_out;

    static int smem_set = 0;
    if (!smem_set) {
        cudaFuncSetAttribute(gemm_kernel, cudaFuncAttributeMaxDynamicSharedMemorySize, SMEM_BYTES);
        smem_set = 1;
    }

    const size_t zero4 = (size_t)N_NODES * N_REL * HID / 4;
    zero_kernel<<<(int)((zero4 + 255) / 256), 256>>>();
    buildW_kernel<<<(NCOL * KPAD + 255) / 256, 256>>>(W_rel, W_root);

    gemm_kernel<<<(N_NODES + BM - 1) / BM, 256, SMEM_BYTES>>>(node_x);

    edge_kernel<<<(N_EDGES * 8) / 256, 256>>>(edge_index, edge_attr);
    node_kernel<<<N_NODES / 8, 256>>>(batch, bias);
    final_kernel<<<1, 64>>>(fc_w, fc_b, out);
}

// round 10
// speedup vs baseline: 4.2462x; 1.1653x over previous
#include <cuda_runtime.h>
#include <cuda_bf16.h>
#include <cstdint>

#define N_NODES  100000
#define N_EDGES  1600000
#define IN_DIM   500
#define KPAD     512
#define HID      32
#define N_REL    7
#define OUT_DIM  4
#define N_GRAPHS 16
#define NCOL     256

// GEMM tiling
#define BM 64
#define BN 256
#define BK 32
#define NITER (KPAD / BK)   // 16
#define PITCH 40            // smem row pitch in bf16 (80B): conflict-free for ldmatrix

// ---------------- scratch (device globals: allocation-free) ----------------
__device__ __nv_bfloat16 g_Hb[(size_t)N_NODES * NCOL]; // 51.2 MB
__device__ float g_O[(size_t)N_NODES * HID];           // 12.8 MB: direct node accum
__device__ float g_cnt[(size_t)N_NODES * N_REL];       // 2.8 MB: counts -> reciprocals
__device__ float g_pool[N_GRAPHS * HID];
__device__ __nv_bfloat16 g_WT[NCOL * KPAD];            // W^T bf16 [n][k], zero-padded

// ---------------- small kernels -------------------------------------------
__global__ void zero_kernel() {
    size_t i = (size_t)blockIdx.x * blockDim.x + threadIdx.x;
    if (i < (size_t)N_NODES * HID / 4)   ((float4*)g_O)[i]   = make_float4(0.f, 0.f, 0.f, 0.f);
    if (i < (size_t)N_NODES * N_REL / 4) ((float4*)g_cnt)[i] = make_float4(0.f, 0.f, 0.f, 0.f);
    if (i < N_GRAPHS * HID) g_pool[i] = 0.0f;
}

__global__ void buildW_kernel(const float* __restrict__ W_rel,
                              const float* __restrict__ W_root) {
    int idx = blockIdx.x * blockDim.x + threadIdx.x;
    if (idx >= NCOL * KPAD) return;
    int n = idx / KPAD;
    int k = idx % KPAD;
    float w = 0.0f;
    if (k < IN_DIM) {
        if (n < HID) w = W_root[k * HID + n];
        else {
            int r = (n - HID) / HID;
            int j = n & (HID - 1);
            w = W_rel[((size_t)r * IN_DIM + k) * HID + j];
        }
    }
    g_WT[idx] = __float2bfloat16(w);
}

__global__ void count_kernel(const int* __restrict__ ei, const int* __restrict__ ea) {
    int e = blockIdx.x * blockDim.x + threadIdx.x;
    if (e >= N_EDGES) return;
    int dst = ei[N_EDGES + e];
    int r   = ea[e];
    if ((unsigned)dst >= N_NODES || (unsigned)r >= N_REL) return;
    atomicAdd(&g_cnt[(size_t)dst * N_REL + r], 1.0f);
}

__global__ void inv_kernel() {
    int i = blockIdx.x * blockDim.x + threadIdx.x;
    if (i < N_NODES * N_REL) g_cnt[i] = 1.0f / fmaxf(g_cnt[i], 1.0f);
}

// ---------------- tensor-core GEMM (2-stage smem, A regs 2-deep) ----------
__device__ __forceinline__ void mma_bf16(float* c, const uint32_t* a, const uint32_t* b) {
    asm volatile(
        "mma.sync.aligned.m16n8k16.row.col.f32.bf16.bf16.f32 "
        "{%0,%1,%2,%3}, {%4,%5,%6,%7}, {%8,%9}, {%0,%1,%2,%3};"
        : "+f"(c[0]), "+f"(c[1]), "+f"(c[2]), "+f"(c[3])
        : "r"(a[0]), "r"(a[1]), "r"(a[2]), "r"(a[3]), "r"(b[0]), "r"(b[1]));
}
__device__ __forceinline__ void ldm_x4(uint32_t* r, uint32_t addr) {
    asm volatile("ldmatrix.sync.aligned.m8n8.x4.shared.b16 {%0,%1,%2,%3}, [%4];"
                 : "=r"(r[0]), "=r"(r[1]), "=r"(r[2]), "=r"(r[3]) : "r"(addr));
}
__device__ __forceinline__ void cp_async16(uint32_t dst, const void* src) {
    asm volatile("cp.async.cg.shared.global [%0], [%1], 16;" :: "r"(dst), "l"(src));
}

// dynamic smem layout (bf16 elems): As[2][BM][PITCH] then Bs[2][BN][PITCH]
#define AS_ELEMS (BM * PITCH)          // 2560
#define BS_ELEMS (BN * PITCH)          // 10240
#define BS_BASE  (2 * AS_ELEMS)        // 5120
#define SMEM_BYTES ((2 * AS_ELEMS + 2 * BS_ELEMS) * 2)   // 51200

__global__ void __launch_bounds__(256, 2) gemm_kernel(const float* __restrict__ A) {
    extern __shared__ __nv_bfloat16 sm[];

    const int tid  = threadIdx.x;
    const int lane = tid & 31;
    const int wid  = tid >> 5;
    const int wm   = wid & 1;            // 2 warp rows x 32
    const int wn   = wid >> 1;           // 4 warp cols x 64
    const int bm   = blockIdx.x * BM;

    float acc[2][8][4];
    #pragma unroll
    for (int i = 0; i < 2; i++)
        #pragma unroll
        for (int j = 0; j < 8; j++)
            #pragma unroll
            for (int q = 0; q < 4; q++) acc[i][j][q] = 0.0f;

    const uint32_t sm_base = (uint32_t)__cvta_generic_to_shared(sm);
    // A load indexing (2 float4 per thread per stage)
    const int ar0 = tid >> 3;            // rows tid/8 and +32
    const int ac4 = tid & 7;
    int gm0 = bm + ar0;      if (gm0 >= N_NODES) gm0 = N_NODES - 1;
    int gm1 = bm + ar0 + 32; if (gm1 >= N_NODES) gm1 = N_NODES - 1;
    const float* aptr0 = A + (size_t)gm0 * IN_DIM + ac4 * 4;
    const float* aptr1 = A + (size_t)gm1 * IN_DIM + ac4 * 4;
    // B cp.async indexing (4 x 16B per thread per stage)
    const int bn_row = tid >> 2;
    const int bq     = tid & 3;
    // ldmatrix lane addressing
    const int a_row  = wm * 32 + (lane & 15);
    const int a_coff = (lane >> 4) * 16;
    const int b_row  = wn * 64 + (lane & 7) + ((lane & 16) >> 1);
    const int b_coff = ((lane >> 3) & 1) * 16;

    float4 abuf0[2], abuf1[2];   // 2-deep register pipeline for A

    // ---- helpers ----
    auto issue_B = [&](int stage, int kt) {
        uint32_t dst = sm_base + (uint32_t)(BS_BASE + stage * BS_ELEMS) * 2;
        #pragma unroll
        for (int i = 0; i < 4; i++) {
            int n = bn_row + i * 64;
            cp_async16(dst + (uint32_t)(n * PITCH + bq * 8) * 2,
                       &g_WT[(size_t)n * KPAD + kt + bq * 8]);
        }
        asm volatile("cp.async.commit_group;");
    };
    auto issue_A = [&](int buf, int kt) {
        if (kt + ac4 * 4 + 3 < IN_DIM) {
            abuf0[buf] = *(const float4*)(aptr0 + kt);
            abuf1[buf] = *(const float4*)(aptr1 + kt);
        } else {
            const float* p0 = aptr0 + kt;
            const float* p1 = aptr1 + kt;
            int k0 = kt + ac4 * 4;
            float4 v0, v1;
            v0.x = (k0 + 0 < IN_DIM) ? p0[0] : 0.f;
            v0.y = (k0 + 1 < IN_DIM) ? p0[1] : 0.f;
            v0.z = (k0 + 2 < IN_DIM) ? p0[2] : 0.f;
            v0.w = (k0 + 3 < IN_DIM) ? p0[3] : 0.f;
            v1.x = (k0 + 0 < IN_DIM) ? p1[0] : 0.f;
            v1.y = (k0 + 1 < IN_DIM) ? p1[1] : 0.f;
            v1.z = (k0 + 2 < IN_DIM) ? p1[2] : 0.f;
            v1.w = (k0 + 3 < IN_DIM) ? p1[3] : 0.f;
            abuf0[buf] = v0; abuf1[buf] = v1;
        }
    };
    auto store_A = [&](int stage, int buf) {
        __nv_bfloat16* as = sm + stage * AS_ELEMS;
        float4 v0 = abuf0[buf], v1 = abuf1[buf];
        __nv_bfloat16 h0[4] = {__float2bfloat16(v0.x), __float2bfloat16(v0.y),
                               __float2bfloat16(v0.z), __float2bfloat16(v0.w)};
        __nv_bfloat16 h1[4] = {__float2bfloat16(v1.x), __float2bfloat16(v1.y),
                               __float2bfloat16(v1.z), __float2bfloat16(v1.w)};
        *(uint2*)&as[ar0 * PITCH + ac4 * 4]        = *(uint2*)h0;
        *(uint2*)&as[(ar0 + 32) * PITCH + ac4 * 4] = *(uint2*)h1;
    };

    // ---- prologue: stage 0 filled; A(1) LDG in flight ----
    issue_B(0, 0);
    issue_A(0, 0);
    store_A(0, 0);
    issue_A(1, BK);                    // A tile 1, consumed at it=0's store
    asm volatile("cp.async.wait_group 0;");
    __syncthreads();

    // ---- main loop (fully unrolled so abuf indices fold) ----
    #pragma unroll
    for (int it = 0; it < NITER; it++) {
        const int cur = it & 1;
        const int nxt = cur ^ 1;
        if (it + 1 < NITER) {
            store_A(nxt, nxt);         // A(it+1): regs loaded 1 iteration ago
            issue_B(nxt, (it + 1) * BK);
        }

        const uint32_t as_st = sm_base + (uint32_t)(cur * AS_ELEMS) * 2;
        const uint32_t bs_st = sm_base + (uint32_t)(BS_BASE + cur * BS_ELEMS) * 2;
        #pragma unroll
        for (int ks = 0; ks < 2; ks++) {
            const int kb = ks * 32;
            uint32_t ah[2][4];
            #pragma unroll
            for (int mi = 0; mi < 2; mi++)
                ldm_x4(ah[mi], as_st + (uint32_t)((a_row + mi * 16) * (PITCH * 2)) + kb + a_coff);
            uint32_t bh[4][4];
            #pragma unroll
            for (int bt = 0; bt < 4; bt++)
                ldm_x4(bh[bt], bs_st + (uint32_t)((b_row + bt * 16) * (PITCH * 2)) + kb + b_coff);
            #pragma unroll
            for (int mi = 0; mi < 2; mi++)
                #pragma unroll
                for (int ni = 0; ni < 8; ni++)
                    mma_bf16(acc[mi][ni], ah[mi], &bh[ni >> 1][(ni & 1) * 2]);
        }

        if (it + 2 < NITER) issue_A(cur, (it + 2) * BK);   // LDG 2 tiles ahead
        if (it + 1 < NITER) asm volatile("cp.async.wait_group 0;");
        __syncthreads();
    }

    // ---- epilogue: store bf16 H ----
    #pragma unroll
    for (int mi = 0; mi < 2; mi++) {
        #pragma unroll
        for (int ni = 0; ni < 8; ni++) {
            int col = wn * 64 + ni * 8 + (lane & 3) * 2;
            int r0  = bm + wm * 32 + mi * 16 + (lane >> 2);
            __nv_bfloat162 v01 = __floats2bfloat162_rn(acc[mi][ni][0], acc[mi][ni][1]);
            __nv_bfloat162 v23 = __floats2bfloat162_rn(acc[mi][ni][2], acc[mi][ni][3]);
            if (r0 < N_NODES)
                *(__nv_bfloat162*)&g_Hb[(size_t)r0 * NCOL + col] = v01;
            if (r0 + 8 < N_NODES)
                *(__nv_bfloat162*)&g_Hb[(size_t)(r0 + 8) * NCOL + col] = v23;
        }
    }
}

// ---------------- edge scatter: O[dst,:] += H[src, rel slice] * inv --------
__global__ void __launch_bounds__(256) edge_kernel(const int* __restrict__ ei,
                                                   const int* __restrict__ ea) {
    int t = blockIdx.x * blockDim.x + threadIdx.x;
    int e = t >> 3;
    int l = t & 7;
    if (e >= N_EDGES) return;
    int src = ei[e];
    int dst = ei[N_EDGES + e];
    int r   = ea[e];
    if ((unsigned)src >= N_NODES || (unsigned)dst >= N_NODES || (unsigned)r >= N_REL) return;
    float inv = __ldg(&g_cnt[(size_t)dst * N_REL + r]);
    const __nv_bfloat162* hp =
        (const __nv_bfloat162*)&g_Hb[(size_t)src * NCOL + (r + 1) * HID + l * 4];
    float2 f0 = __bfloat1622float2(hp[0]);
    float2 f1 = __bfloat1622float2(hp[1]);
    float* op = &g_O[(size_t)dst * HID + l * 4];
    asm volatile("red.global.add.v4.f32 [%0], {%1, %2, %3, %4};"
                 :: "l"(op), "f"(f0.x * inv), "f"(f0.y * inv),
                    "f"(f1.x * inv), "f"(f1.y * inv) : "memory");
}

// ---------------- node combine + relu + pool -------------------------------
__global__ void __launch_bounds__(256) node_kernel(const int* __restrict__ batch,
                                                   const float* __restrict__ bias) {
    int n = blockIdx.x * 8 + (threadIdx.x >> 5);
    int j = threadIdx.x & 31;
    if (n >= N_NODES) return;
    float v = __bfloat162float(g_Hb[(size_t)n * NCOL + j]) + bias[j]
            + g_O[(size_t)n * HID + j];
    v = fmaxf(v, 0.0f);
    int g = batch[n];
    if ((unsigned)g >= N_GRAPHS) return;
    atomicAdd(&g_pool[g * HID + j], v);
}

// ---------------- final: out[16,4] = pool[16,32] @ fc_w[32,4] + fc_b -------
__global__ void final_kernel(const float* __restrict__ fc_w,
                             const float* __restrict__ fc_b,
                             float* __restrict__ out) {
    int t = threadIdx.x;
    if (t >= N_GRAPHS * OUT_DIM) return;
    int g = t / OUT_DIM, o = t % OUT_DIM;
    float s = fc_b[o];
    #pragma unroll
    for (int h = 0; h < HID; h++)
        s += g_pool[g * HID + h] * fc_w[h * OUT_DIM + o];
    out[t] = s;
}

// ---------------- launch ----------------------------------------------------
extern "C" void kernel_launch(void* const* d_in, const int* in_sizes, int n_in,
                              void* d_out, int out_size) {
    const float* node_x     = 0;  // 50,000,000
    const int*   edge_index = 0;  //  3,200,000
    const int*   edge_attr  = 0;  //  1,600,000
    const int*   batch      = 0;  //    100,000
    const float* W_rel      = 0;  //    112,000
    const float* W_root     = 0;  //     16,000
    const float* bias       = 0;  //         32
    const float* fc_w       = 0;  //        128
    const float* fc_b       = 0;  //          4

    for (int i = 0; i < n_in; i++) {
        switch (in_sizes[i]) {
            case 50000000: node_x     = (const float*)d_in[i]; break;
            case  3200000: edge_index = (const int*)d_in[i];   break;
            case  1600000: edge_attr  = (const int*)d_in[i];   break;
            case   100000: batch      = (const int*)d_in[i];   break;
            case   112000: W_rel      = (const float*)d_in[i]; break;
            case    16000: W_root     = (const float*)d_in[i]; break;
            case       32: bias       = (const float*)d_in[i]; break;
            case      128: fc_w       = (const float*)d_in[i]; break;
            case        4: fc_b       = (const float*)d_in[i]; break;
            default: break;
        }
    }
    float* out = (float*)d_out;

    static int smem_set = 0;
    if (!smem_set) {
        cudaFuncSetAttribute(gemm_kernel, cudaFuncAttributeMaxDynamicSharedMemorySize, SMEM_BYTES);
        smem_set = 1;
    }

    zero_kernel<<<(N_NODES * HID / 4 + 255) / 256, 256>>>();
    buildW_kernel<<<(NCOL * KPAD + 255) / 256, 256>>>(W_rel, W_root);
    count_kernel<<<(N_EDGES + 255) / 256, 256>>>(edge_index, edge_attr);
    inv_kernel<<<(N_NODES * N_REL + 255) / 256, 256>>>();

    gemm_kernel<<<(N_NODES + BM - 1) / BM, 256, SMEM_BYTES>>>(node_x);

    edge_kernel<<<(N_EDGES * 8) / 256, 256>>>(edge_index, edge_attr);
    node_kernel<<<N_NODES / 8, 256>>>(batch, bias);
    final_kernel<<<1, 64>>>(fc_w, fc_b, out);
}